// round 14
// baseline (speedup 1.0000x reference)
#include <cuda_runtime.h>
#include <cstdint>

// Problem constants
#define Bq     8
#define NIN    512
#define NOUT   1024
#define Cc     16
#define OUTC   32
#define KW     5

// Fused kernel tiling
#define MTILE  64                 // m per block
#define MT     (NOUT / MTILE)     // 16
#define GRIDB  (Bq * MT)          // 128 blocks (1/SM, co-resident)
#define GTHREADS 512              // 16 warps: 4 m-subtiles x 4 k-quarters
#define KQ     4
#define KSTEPS 16                 // (NIN/KQ)/8
#define CSL    32                 // conv n-slice per block

#define LOG2E 1.4426950408889634f

// conv output, PER-THREAD FRAGMENT ORDER for the gauss MMA:
// off(n,c) = (n>>6)*1024 + ((n&63)>>3)*128 + ((c&7)*4+(n&3))*4
//            + ((n>>2)&1) + 2*(c>>3)
__device__ float g_rt[Bq * NIN * Cc];
__device__ unsigned g_bar;   // monotonic grid-barrier ticket counter

__device__ __forceinline__ float ex2a(float x) {
    float r; asm("ex2.approx.f32 %0, %1;" : "=f"(r) : "f"(x)); return r;
}
__device__ __forceinline__ unsigned f2tf32(float x) {
    unsigned r; asm("cvt.rna.tf32.f32 %0, %1;" : "=r"(r) : "f"(x)); return r;
}
__device__ __forceinline__ void mma_tf32(float d[4], const unsigned a[4],
                                         unsigned b0, unsigned b1) {
    asm volatile(
        "mma.sync.aligned.m16n8k8.row.col.f32.tf32.tf32.f32 "
        "{%0,%1,%2,%3}, {%4,%5,%6,%7}, {%8,%9}, {%0,%1,%2,%3};"
        : "+f"(d[0]), "+f"(d[1]), "+f"(d[2]), "+f"(d[3])
        : "r"(a[0]), "r"(a[1]), "r"(a[2]), "r"(a[3]), "r"(b0), "r"(b1));
}

__device__ __forceinline__ int rt_off(int n, int c) {
    return (n >> 6) * 1024 + ((n & 63) >> 3) * 128 +
           (((c & 7) << 2) + (n & 3)) * 4 + ((n >> 2) & 1) + 2 * (c >> 3);
}

// ---------------------------------------------------------------------------
// Fused kernel: conv slice -> grid barrier (load-poll) -> gauss MMA + linear.
// grid 128 blocks (1 per SM, all co-resident), block 512.
// Block blk: b = blk>>4, mt = blk&15 (doubles as conv n-slice index).
// ---------------------------------------------------------------------------
__global__ void __launch_bounds__(GTHREADS, 1)
fused_kernel(const float* __restrict__ r,
             const float* __restrict__ conv_w,
             const float* __restrict__ conv_b,
             const float* __restrict__ xc,
             const float* __restrict__ xt,
             const float* __restrict__ sigma,
             const float* __restrict__ lw,
             const float* __restrict__ lb,
             float* __restrict__ out) {
    __shared__ float csr[Cc][CSL + 4];                     // conv input slice
    __shared__ float csw[Cc * Cc * KW];                    // raw weights
    __shared__ float csb[Cc];
    __shared__ __align__(16) float cfrag[CSL * Cc];        // staged conv slice
    __shared__ __align__(16) float zred[KQ][MTILE][Cc];    // 16 KB partials
    __shared__ __align__(16) float shlwT[Cc * OUTC];       // transposed [c][o]
    __shared__ float sh_nh[Cc];
    __shared__ int   sh_alleq;

    const int blk = blockIdx.x;
    const int b   = blk >> 4;
    const int mt  = blk & 15;
    const int t   = threadIdx.x;
    const int l   = t & 31;
    const int w   = t >> 5;

    // ---------------- Phase 1: conv slice (32 n x 16 c, 1 output/thread) ----
    for (int i = t; i < Cc * (CSL + 4); i += GTHREADS) {
        int ci = i / (CSL + 4);
        int j  = i % (CSL + 4);
        int n  = mt * CSL + j - 2;
        csr[ci][j] = (n >= 0 && n < NIN) ? r[((size_t)b * Cc + ci) * NIN + n] : 0.0f;
    }
    for (int i = t; i < Cc * Cc * KW; i += GTHREADS) csw[i] = conv_w[i];
    if (t < Cc) csb[t] = conv_b[t];
    // gauss constants prepared during conv phase
    if (t >= 32 && t < 32 + Cc) {
        float sg = sigma[t - 32];
        sh_nh[t - 32] = -0.5f * expf(-2.0f * sg) * LOG2E;
    }
    if (t == 64) {
        float s0 = sigma[0];
        int eq = 1;
        #pragma unroll
        for (int c = 1; c < Cc; c++) eq &= (sigma[c] == s0);
        sh_alleq = eq;
    }
    if (t < Cc * OUTC) {
        int c = t >> 5, o = t & 31;
        shlwT[t] = lw[o * Cc + c];
    }
    __syncthreads();

    const int slice_base = ((mt * CSL) >> 6) * 1024 + (((mt * CSL) & 63) >> 3) * 128;
    {
        const int c  = t & 15;        // out channel
        const int nl = t >> 4;        // 0..31 local n
        float a = csb[c];
        #pragma unroll
        for (int ci = 0; ci < Cc; ci++) {
            #pragma unroll
            for (int k = 0; k < KW; k++)
                a += csr[ci][nl + k] * csw[c * (Cc * KW) + ci * KW + k];
        }
        // stage at fragment-relative offset (scattered STS is cheap)
        cfrag[rt_off(mt * CSL + nl, c) - slice_base] = __uint_as_float(f2tf32(a));
    }
    __syncthreads();
    // coalesced write-out: 128 threads x 1 float4 = whole 512-float slice
    if (t < 128) {
        reinterpret_cast<float4*>(g_rt + (size_t)b * NIN * Cc + slice_base)[t] =
            reinterpret_cast<const float4*>(cfrag)[t];
    }

    // ---------------- Grid barrier: ticket arrival + acquire-load polling ---
    __threadfence();
    __syncthreads();
    if (t == 0) {
        unsigned val = atomicAdd(&g_bar, 1u);
        unsigned target = (val / (unsigned)GRIDB + 1u) * (unsigned)GRIDB;
        for (;;) {
            unsigned cur;
            asm volatile("ld.acquire.gpu.u32 %0, [%1];"
                         : "=r"(cur) : "l"(&g_bar));
            if (cur >= target) break;
            __nanosleep(64);
        }
    }
    __syncthreads();

    // ---------------- Phase 2: gauss MMA (proven R11/R13 body) --------------
    const int msub = w & 3;
    const int kq   = w >> 2;

    if (sh_alleq) {
        const float nh = sh_nh[0];
        const int mrow = mt * MTILE + msub * 16 + (l >> 2);
        const float xm0 = __ldg(xt + (size_t)b * NOUT + mrow);
        const float xm1 = __ldg(xt + (size_t)b * NOUT + mrow + 8);

        // preload B fragments: 16 coalesced LDG.128/thread via L2 (__ldcg)
        const float4* Bg = reinterpret_cast<const float4*>(
            g_rt + (size_t)b * NIN * Cc + kq * 2048);
        float4 Bf[KSTEPS];
        #pragma unroll
        for (int ks = 0; ks < KSTEPS; ks++)
            Bf[ks] = __ldcg(&Bg[(ks >> 3) * 256 + (ks & 7) * 32 + l]);

        // preload x-context for this warp's 128 n (coalesced, 4 regs)
        const float* xcb = xc + (size_t)b * NIN + kq * 128;
        float xr0 = __ldg(xcb + l);
        float xr1 = __ldg(xcb + 32 + l);
        float xr2 = __ldg(xcb + 64 + l);
        float xr3 = __ldg(xcb + 96 + l);

        float D0[4] = {0.f, 0.f, 0.f, 0.f};
        float D1[4] = {0.f, 0.f, 0.f, 0.f};

        #pragma unroll
        for (int ks = 0; ks < KSTEPS; ks++) {
            const float xsrc = (ks < 8) ? ((ks < 4) ? xr0 : xr1)
                                        : ((ks < 12) ? xr2 : xr3);
            const int srca = (ks & 3) * 8 + (l & 3);
            float xna = __shfl_sync(0xffffffffu, xsrc, srca);
            float xnb = __shfl_sync(0xffffffffu, xsrc, srca + 4);
            unsigned A[4];
            float d;
            // ex2 bits used directly as tf32 (HW truncates) — no CVT in chain
            d = xm0 - xna; A[0] = __float_as_uint(ex2a(d * d * nh));
            d = xm1 - xna; A[1] = __float_as_uint(ex2a(d * d * nh));
            d = xm0 - xnb; A[2] = __float_as_uint(ex2a(d * d * nh));
            d = xm1 - xnb; A[3] = __float_as_uint(ex2a(d * d * nh));
            mma_tf32(D0, A, __float_as_uint(Bf[ks].x), __float_as_uint(Bf[ks].y));
            mma_tf32(D1, A, __float_as_uint(Bf[ks].z), __float_as_uint(Bf[ks].w));
        }

        const int ml = msub * 16 + (l >> 2);
        const int c0 = (l & 3) * 2;
        *reinterpret_cast<float2*>(&zred[kq][ml][c0])         = make_float2(D0[0], D0[1]);
        *reinterpret_cast<float2*>(&zred[kq][ml + 8][c0])     = make_float2(D0[2], D0[3]);
        *reinterpret_cast<float2*>(&zred[kq][ml][c0 + 8])     = make_float2(D1[0], D1[1]);
        *reinterpret_cast<float2*>(&zred[kq][ml + 8][c0 + 8]) = make_float2(D1[2], D1[3]);
    } else {
        // generic per-channel sigma fallback (correct, not fast)
        float nhc[8];
        const int chalf = l & 1;
        #pragma unroll
        for (int j = 0; j < 8; j++) nhc[j] = sh_nh[chalf * 8 + j];
        const int mloc = msub * 16 + (l >> 1);
        const float xm = __ldg(xt + (size_t)b * NOUT + mt * MTILE + mloc);
        const float* rtb = g_rt + (size_t)b * NIN * Cc;
        float acc[8];
        #pragma unroll
        for (int j = 0; j < 8; j++) acc[j] = 0.0f;
        for (int i = 0; i < NIN / KQ; i++) {
            const int n = kq * (NIN / KQ) + i;
            float dx = xm - __ldg(xc + (size_t)b * NIN + n);
            float d  = dx * dx;
            #pragma unroll
            for (int j = 0; j < 8; j++) {
                int c = chalf * 8 + j;
                acc[j] += ex2a(d * nhc[j]) * __ldcg(rtb + rt_off(n, c));
            }
        }
        float* zp = &zred[kq][mloc][chalf * 8];
        *reinterpret_cast<float4*>(zp)     = make_float4(acc[0], acc[1], acc[2], acc[3]);
        *reinterpret_cast<float4*>(zp + 4) = make_float4(acc[4], acc[5], acc[6], acc[7]);
    }
    __syncthreads();

    // fold 4 partial sets into set 0 (256 threads, 1 float4 each)
    {
        float4* rv = reinterpret_cast<float4*>(zred);
        const int NV = MTILE * Cc / 4;   // 256 slots per set
        if (t < NV) {
            float4 s = rv[t];
            #pragma unroll
            for (int q = 1; q < KQ; q++) {
                float4 p = rv[q * NV + t];
                s.x += p.x; s.y += p.y; s.z += p.z; s.w += p.w;
            }
            rv[t] = s;
        }
    }
    __syncthreads();

    // linear C -> OUT_C + bias: thread t -> (ml = t>>3, 4 outputs at og=(t&7)*4)
    {
        const int ml = t >> 3;            // 0..63
        const int og = (t & 7) * 4;       // 0..28
        float z[Cc];
        #pragma unroll
        for (int c = 0; c < Cc; c += 4) {
            float4 zv = *reinterpret_cast<const float4*>(&zred[0][ml][c]);
            z[c] = zv.x; z[c + 1] = zv.y; z[c + 2] = zv.z; z[c + 3] = zv.w;
        }
        float4 o4;
        o4.x = __ldg(lb + og + 0); o4.y = __ldg(lb + og + 1);
        o4.z = __ldg(lb + og + 2); o4.w = __ldg(lb + og + 3);
        #pragma unroll
        for (int c = 0; c < Cc; c++) {
            float zc = z[c];
            float4 wv = *reinterpret_cast<const float4*>(&shlwT[c * OUTC + og]);
            o4.x += zc * wv.x; o4.y += zc * wv.y;
            o4.z += zc * wv.z; o4.w += zc * wv.w;
        }
        *reinterpret_cast<float4*>(
            out + (((size_t)b * NOUT) + mt * MTILE + ml) * OUTC + og) = o4;
    }
}

// ---------------------------------------------------------------------------
// Launch. Inputs (metadata order):
// 0 r (8,16,512) | 1 x_context (8,512,1) | 2 y_context (unused) |
// 3 x_target (8,1024,1) | 4 conv_w (16,16,5) | 5 conv_b (16) |
// 6 sigma (16) | 7 lin_w (32,16) | 8 lin_b (32)  -> out (8,1024,32) f32
// ---------------------------------------------------------------------------
extern "C" void kernel_launch(void* const* d_in, const int* in_sizes, int n_in,
                              void* d_out, int out_size) {
    const float* r      = (const float*)d_in[0];
    const float* xc     = (const float*)d_in[1];
    const float* xt     = (const float*)d_in[3];
    const float* conv_w = (const float*)d_in[4];
    const float* conv_b = (const float*)d_in[5];
    const float* sigma  = (const float*)d_in[6];
    const float* lin_w  = (const float*)d_in[7];
    const float* lin_b  = (const float*)d_in[8];
    float* out = (float*)d_out;

    fused_kernel<<<GRIDB, GTHREADS>>>(r, conv_w, conv_b, xc, xt, sigma,
                                      lin_w, lin_b, out);
}

// round 15
// speedup vs baseline: 1.1250x; 1.1250x over previous
#include <cuda_runtime.h>
#include <cstdint>

// Problem constants
#define Bq     8
#define NIN    512
#define NOUT   1024
#define Cc     16
#define OUTC   32
#define KW     5

// Conv tiling
#define CNTILE 32
#define CTHREADS 128

// Gauss-MMA tiling
#define MTILE  64                 // m per block
#define MT     (NOUT / MTILE)     // 16
#define GTHREADS 512              // 16 warps: 4 m-subtiles x 4 k-quarters
#define KQ     4
#define KSTEPS 16                 // (NIN/KQ)/8

#define LOG2E 1.4426950408889634f

// conv output, stored in PER-THREAD FRAGMENT ORDER for the gauss MMA:
// off(n,c) = (n>>6)*1024 + ((n&63)>>3)*128 + ((c&7)*4+(n&3))*4
//            + ((n>>2)&1) + 2*(c>>3)
__device__ float g_rt[Bq * NIN * Cc];

__device__ __forceinline__ float ex2a(float x) {
    float r; asm("ex2.approx.f32 %0, %1;" : "=f"(r) : "f"(x)); return r;
}
__device__ __forceinline__ unsigned f2tf32(float x) {
    unsigned r; asm("cvt.rna.tf32.f32 %0, %1;" : "=r"(r) : "f"(x)); return r;
}
__device__ __forceinline__ void mma_tf32(float d[4], const unsigned a[4],
                                         unsigned b0, unsigned b1) {
    asm volatile(
        "mma.sync.aligned.m16n8k8.row.col.f32.tf32.tf32.f32 "
        "{%0,%1,%2,%3}, {%4,%5,%6,%7}, {%8,%9}, {%0,%1,%2,%3};"
        : "+f"(d[0]), "+f"(d[1]), "+f"(d[2]), "+f"(d[3])
        : "r"(a[0]), "r"(a[1]), "r"(a[2]), "r"(a[3]), "r"(b0), "r"(b1));
}

__device__ __forceinline__ int rt_off(int n, int c) {
    return (n >> 6) * 1024 + ((n & 63) >> 3) * 128 +
           (((c & 7) << 2) + (n & 3)) * 4 + ((n >> 2) & 1) + 2 * (c >> 3);
}

// ---------------------------------------------------------------------------
// Kernel 1: Conv1d (NCH, OIH, SAME pad=2) + bias -> g_rt (tf32-rounded,
// fragment-ordered, coalesced write-out). grid (16, 8), block 128.
// Signals dependent-grid launch immediately after its stores (PDL).
// ---------------------------------------------------------------------------
__global__ void conv_kernel(const float* __restrict__ r,
                            const float* __restrict__ w,
                            const float* __restrict__ bias) {
    __shared__ float sr[Cc][CNTILE + 4];
    __shared__ float sws[Cc * KW * Cc];   // [ci][k][c_out]
    __shared__ float sb[Cc];
    __shared__ __align__(16) float cfrag[CNTILE * Cc];   // 512 staged outputs

    const int b  = blockIdx.y;
    const int n0 = blockIdx.x * CNTILE;
    const int t  = threadIdx.x;

    for (int i = t; i < Cc * (CNTILE + 4); i += CTHREADS) {
        int ci = i / (CNTILE + 4);
        int j  = i % (CNTILE + 4);
        int n  = n0 + j - 2;
        sr[ci][j] = (n >= 0 && n < NIN) ? r[((size_t)b * Cc + ci) * NIN + n] : 0.0f;
    }
    for (int i = t; i < Cc * Cc * KW; i += CTHREADS) {
        int c  = i / (Cc * KW);
        int rm = i % (Cc * KW);
        int ci = rm / KW;
        int k  = rm % KW;
        sws[(ci * KW + k) * Cc + c] = w[i];
    }
    if (t < Cc) sb[t] = bias[t];
    __syncthreads();

    const int nl = t & (CNTILE - 1);
    const int cg = t >> 5;            // 0..3, channels cg*4..cg*4+3
    const int n  = n0 + nl;

    float a[4];
    #pragma unroll
    for (int q = 0; q < 4; q++) a[q] = sb[cg * 4 + q];

    #pragma unroll
    for (int k = 0; k < KW; k++) {
        #pragma unroll
        for (int ci = 0; ci < Cc; ci++) {
            float v = sr[ci][nl + k];
            float4 wv = *reinterpret_cast<const float4*>(&sws[(ci * KW + k) * Cc + cg * 4]);
            a[0] += v * wv.x; a[1] += v * wv.y; a[2] += v * wv.z; a[3] += v * wv.w;
        }
    }

    // stage into smem at fragment-relative offsets (scattered STS is cheap)
    const int slice_base = (n0 >> 6) * 1024 + ((n0 & 63) >> 3) * 128;
    #pragma unroll
    for (int q = 0; q < 4; q++) {
        int c = cg * 4 + q;
        cfrag[rt_off(n, c) - slice_base] = __uint_as_float(f2tf32(a[q]));
    }
    __syncthreads();

    // coalesced write-out: 128 threads x 1 float4 = the whole 512-float slice
    {
        const float4* cf4 = reinterpret_cast<const float4*>(cfrag);
        float4* dst4 = reinterpret_cast<float4*>(
            g_rt + (size_t)b * NIN * Cc + slice_base);
        dst4[t] = cf4[t];
    }

    // PDL: allow the dependent (gauss) grid to launch now
    asm volatile("griddepcontrol.launch_dependents;");
}

// ---------------------------------------------------------------------------
// Kernel 2: Gaussian transform as tf32 MMA + 2-stage reduce + linear.
// Launched with programmatic dependent launch: its prologue (constants,
// weights, xm/xc loads) overlaps conv; griddepcontrol.wait guards the only
// conv-dependent reads (g_rt fragment preloads, via __ldcg).
// grid (MT, B) = (16, 8) = 128 blocks, block 512 (16 warps).
// ---------------------------------------------------------------------------
__global__ void __launch_bounds__(GTHREADS, 1)
gauss_mma_kernel(const float* __restrict__ xc,
                 const float* __restrict__ xt,
                 const float* __restrict__ sigma,
                 const float* __restrict__ lw,
                 const float* __restrict__ lb,
                 float* __restrict__ out) {
    __shared__ __align__(16) float zred[KQ][MTILE][Cc];   // 16 KB partials
    __shared__ __align__(16) float shlwT[Cc * OUTC];      // 2 KB transposed [c][o]
    __shared__ float sh_nh[Cc];
    __shared__ int   sh_alleq;

    const int b  = blockIdx.y;
    const int mt = blockIdx.x;
    const int t  = threadIdx.x;
    const int l  = t & 31;
    const int w  = t >> 5;
    const int msub = w & 3;
    const int kq   = w >> 2;

    if (t < Cc) {
        float sg = sigma[t];
        sh_nh[t] = -0.5f * expf(-2.0f * sg) * LOG2E;
    }
    if (t == 0) {
        float s0 = sigma[0];
        int eq = 1;
        #pragma unroll
        for (int c = 1; c < Cc; c++) eq &= (sigma[c] == s0);
        sh_alleq = eq;
    }
    // transposed linear weights: shlwT[c*OUTC + o] = lw[o*Cc + c]
    if (t < Cc * OUTC) {
        int c = t >> 5, o = t & 31;
        shlwT[t] = lw[o * Cc + c];
    }
    __syncthreads();

    if (sh_alleq) {
        // ---- tf32 MMA fast path: register-resident hot loop ----
        const float nh = sh_nh[0];
        const int mrow = mt * MTILE + msub * 16 + (l >> 2);
        const float xm0 = __ldg(xt + (size_t)b * NOUT + mrow);
        const float xm1 = __ldg(xt + (size_t)b * NOUT + mrow + 8);

        // preload x-context for this warp's 128 n (independent of conv)
        const float* xcb = xc + (size_t)b * NIN + kq * 128;
        float xr0 = __ldg(xcb + l);
        float xr1 = __ldg(xcb + 32 + l);
        float xr2 = __ldg(xcb + 64 + l);
        float xr3 = __ldg(xcb + 96 + l);

        // wait for the primary (conv) grid before touching g_rt
        asm volatile("griddepcontrol.wait;" ::: "memory");

        // preload B fragments: 16 coalesced LDG.128/thread via L2 (__ldcg)
        const float4* Bg = reinterpret_cast<const float4*>(
            g_rt + (size_t)b * NIN * Cc + kq * 2048);
        float4 Bf[KSTEPS];
        #pragma unroll
        for (int ks = 0; ks < KSTEPS; ks++)
            Bf[ks] = __ldcg(&Bg[(ks >> 3) * 256 + (ks & 7) * 32 + l]);

        float D0[4] = {0.f, 0.f, 0.f, 0.f};
        float D1[4] = {0.f, 0.f, 0.f, 0.f};

        #pragma unroll
        for (int ks = 0; ks < KSTEPS; ks++) {
            const float xsrc = (ks < 8) ? ((ks < 4) ? xr0 : xr1)
                                        : ((ks < 12) ? xr2 : xr3);
            const int srca = (ks & 3) * 8 + (l & 3);
            float xna = __shfl_sync(0xffffffffu, xsrc, srca);
            float xnb = __shfl_sync(0xffffffffu, xsrc, srca + 4);
            unsigned A[4];
            float d;
            // ex2 bits used directly as tf32 (HW truncates) — no CVT in chain
            d = xm0 - xna; A[0] = __float_as_uint(ex2a(d * d * nh));
            d = xm1 - xna; A[1] = __float_as_uint(ex2a(d * d * nh));
            d = xm0 - xnb; A[2] = __float_as_uint(ex2a(d * d * nh));
            d = xm1 - xnb; A[3] = __float_as_uint(ex2a(d * d * nh));
            mma_tf32(D0, A, __float_as_uint(Bf[ks].x), __float_as_uint(Bf[ks].y));
            mma_tf32(D1, A, __float_as_uint(Bf[ks].z), __float_as_uint(Bf[ks].w));
        }

        const int ml = msub * 16 + (l >> 2);
        const int c0 = (l & 3) * 2;
        *reinterpret_cast<float2*>(&zred[kq][ml][c0])         = make_float2(D0[0], D0[1]);
        *reinterpret_cast<float2*>(&zred[kq][ml + 8][c0])     = make_float2(D0[2], D0[3]);
        *reinterpret_cast<float2*>(&zred[kq][ml][c0 + 8])     = make_float2(D1[0], D1[1]);
        *reinterpret_cast<float2*>(&zred[kq][ml + 8][c0 + 8]) = make_float2(D1[2], D1[3]);
    } else {
        // ---- generic per-channel sigma fallback (correct, not fast) ----
        asm volatile("griddepcontrol.wait;" ::: "memory");
        float nhc[8];
        const int chalf = l & 1;
        #pragma unroll
        for (int j = 0; j < 8; j++) nhc[j] = sh_nh[chalf * 8 + j];
        const int mloc = msub * 16 + (l >> 1);
        const float xm = __ldg(xt + (size_t)b * NOUT + mt * MTILE + mloc);
        const float* rtb = g_rt + (size_t)b * NIN * Cc;
        float acc[8];
        #pragma unroll
        for (int j = 0; j < 8; j++) acc[j] = 0.0f;
        for (int i = 0; i < NIN / KQ; i++) {
            const int n = kq * (NIN / KQ) + i;
            float dx = xm - __ldg(xc + (size_t)b * NIN + n);
            float d  = dx * dx;
            #pragma unroll
            for (int j = 0; j < 8; j++) {
                int c = chalf * 8 + j;
                acc[j] += ex2a(d * nhc[j]) * __ldcg(rtb + rt_off(n, c));
            }
        }
        float* zp = &zred[kq][mloc][chalf * 8];
        *reinterpret_cast<float4*>(zp)     = make_float4(acc[0], acc[1], acc[2], acc[3]);
        *reinterpret_cast<float4*>(zp + 4) = make_float4(acc[4], acc[5], acc[6], acc[7]);
    }
    __syncthreads();

    // Stage A: fold 4 partial sets into set 0 (256 threads, 1 float4 each)
    {
        float4* rv = reinterpret_cast<float4*>(zred);
        const int NV = MTILE * Cc / 4;   // 256 slots per set
        if (t < NV) {
            float4 s = rv[t];
            #pragma unroll
            for (int q = 1; q < KQ; q++) {
                float4 p = rv[q * NV + t];
                s.x += p.x; s.y += p.y; s.z += p.z; s.w += p.w;
            }
            rv[t] = s;
        }
    }
    __syncthreads();

    // linear C -> OUT_C + bias: thread t -> (ml = t>>3, 4 outputs at og=(t&7)*4)
    {
        const int ml = t >> 3;            // 0..63
        const int og = (t & 7) * 4;       // 0..28
        float z[Cc];
        #pragma unroll
        for (int c = 0; c < Cc; c += 4) {
            float4 zv = *reinterpret_cast<const float4*>(&zred[0][ml][c]);
            z[c] = zv.x; z[c + 1] = zv.y; z[c + 2] = zv.z; z[c + 3] = zv.w;
        }
        float4 o4;
        o4.x = __ldg(lb + og + 0); o4.y = __ldg(lb + og + 1);
        o4.z = __ldg(lb + og + 2); o4.w = __ldg(lb + og + 3);
        #pragma unroll
        for (int c = 0; c < Cc; c++) {
            float zc = z[c];
            float4 wv = *reinterpret_cast<const float4*>(&shlwT[c * OUTC + og]);
            o4.x += zc * wv.x; o4.y += zc * wv.y;
            o4.z += zc * wv.z; o4.w += zc * wv.w;
        }
        *reinterpret_cast<float4*>(
            out + (((size_t)b * NOUT) + mt * MTILE + ml) * OUTC + og) = o4;
    }
}

// ---------------------------------------------------------------------------
// Launch. Inputs (metadata order):
// 0 r (8,16,512) | 1 x_context (8,512,1) | 2 y_context (unused) |
// 3 x_target (8,1024,1) | 4 conv_w (16,16,5) | 5 conv_b (16) |
// 6 sigma (16) | 7 lin_w (32,16) | 8 lin_b (32)  -> out (8,1024,32) f32
// Gauss is launched with Programmatic Dependent Launch so its prologue
// overlaps conv; griddepcontrol.wait in-kernel guards the g_rt reads.
// ---------------------------------------------------------------------------
extern "C" void kernel_launch(void* const* d_in, const int* in_sizes, int n_in,
                              void* d_out, int out_size) {
    const float* r      = (const float*)d_in[0];
    const float* xc     = (const float*)d_in[1];
    const float* xt     = (const float*)d_in[3];
    const float* conv_w = (const float*)d_in[4];
    const float* conv_b = (const float*)d_in[5];
    const float* sigma  = (const float*)d_in[6];
    const float* lin_w  = (const float*)d_in[7];
    const float* lin_b  = (const float*)d_in[8];
    float* out = (float*)d_out;

    conv_kernel<<<dim3(NIN / CNTILE, Bq), CTHREADS>>>(r, conv_w, conv_b);

    cudaLaunchConfig_t cfg = {};
    cfg.gridDim  = dim3(MT, Bq);
    cfg.blockDim = dim3(GTHREADS);
    cfg.dynamicSmemBytes = 0;
    cfg.stream = 0;
    cudaLaunchAttribute attrs[1];
    attrs[0].id = cudaLaunchAttributeProgrammaticStreamSerialization;
    attrs[0].val.programmaticStreamSerializationAllowed = 1;
    cfg.attrs = attrs;
    cfg.numAttrs = 1;
    cudaLaunchKernelEx(&cfg, gauss_mma_kernel, xc, xt, sigma, lin_w, lin_b, out);
}

// round 16
// speedup vs baseline: 1.1278x; 1.0025x over previous
#include <cuda_runtime.h>
#include <cstdint>

// Problem constants
#define Bq     8
#define NIN    512
#define NOUT   1024
#define Cc     16
#define OUTC   32
#define KW     5

// Conv tiling
#define CNTILE 32
#define CTHREADS 128

// Gauss-MMA tiling
#define MTILE  64                 // m per block
#define MT     (NOUT / MTILE)     // 16
#define GTHREADS 512              // 16 warps: 4 m-subtiles x 4 k-quarters
#define KQ     4
#define KSTEPS 16                 // (NIN/KQ)/8
#define BWIN   4                  // Bf prefetch window

#define LOG2E 1.4426950408889634f

// conv output, stored in PER-THREAD FRAGMENT ORDER for the gauss MMA:
// off(n,c) = (n>>6)*1024 + ((n&63)>>3)*128 + ((c&7)*4+(n&3))*4
//            + ((n>>2)&1) + 2*(c>>3)
__device__ float g_rt[Bq * NIN * Cc];

__device__ __forceinline__ float ex2a(float x) {
    float r; asm("ex2.approx.f32 %0, %1;" : "=f"(r) : "f"(x)); return r;
}
__device__ __forceinline__ unsigned f2tf32(float x) {
    unsigned r; asm("cvt.rna.tf32.f32 %0, %1;" : "=r"(r) : "f"(x)); return r;
}
__device__ __forceinline__ void mma_tf32(float d[4], const unsigned a[4],
                                         unsigned b0, unsigned b1) {
    asm volatile(
        "mma.sync.aligned.m16n8k8.row.col.f32.tf32.tf32.f32 "
        "{%0,%1,%2,%3}, {%4,%5,%6,%7}, {%8,%9}, {%0,%1,%2,%3};"
        : "+f"(d[0]), "+f"(d[1]), "+f"(d[2]), "+f"(d[3])
        : "r"(a[0]), "r"(a[1]), "r"(a[2]), "r"(a[3]), "r"(b0), "r"(b1));
}

__device__ __forceinline__ int rt_off(int n, int c) {
    return (n >> 6) * 1024 + ((n & 63) >> 3) * 128 +
           (((c & 7) << 2) + (n & 3)) * 4 + ((n >> 2) & 1) + 2 * (c >> 3);
}

// ---------------------------------------------------------------------------
// Kernel 1: Conv1d (NCH, OIH, SAME pad=2) + bias -> g_rt (tf32-rounded,
// fragment-ordered, coalesced write-out). grid (16, 8), block 128.
// Signals dependent-grid progress via PDL after its stores.
// ---------------------------------------------------------------------------
__global__ void conv_kernel(const float* __restrict__ r,
                            const float* __restrict__ w,
                            const float* __restrict__ bias) {
    __shared__ float sr[Cc][CNTILE + 4];
    __shared__ float sws[Cc * KW * Cc];   // [ci][k][c_out]
    __shared__ float sb[Cc];
    __shared__ __align__(16) float cfrag[CNTILE * Cc];   // 512 staged outputs

    const int b  = blockIdx.y;
    const int n0 = blockIdx.x * CNTILE;
    const int t  = threadIdx.x;

    for (int i = t; i < Cc * (CNTILE + 4); i += CTHREADS) {
        int ci = i / (CNTILE + 4);
        int j  = i % (CNTILE + 4);
        int n  = n0 + j - 2;
        sr[ci][j] = (n >= 0 && n < NIN) ? r[((size_t)b * Cc + ci) * NIN + n] : 0.0f;
    }
    for (int i = t; i < Cc * Cc * KW; i += CTHREADS) {
        int c  = i / (Cc * KW);
        int rm = i % (Cc * KW);
        int ci = rm / KW;
        int k  = rm % KW;
        sws[(ci * KW + k) * Cc + c] = w[i];
    }
    if (t < Cc) sb[t] = bias[t];
    __syncthreads();

    const int nl = t & (CNTILE - 1);
    const int cg = t >> 5;            // 0..3, channels cg*4..cg*4+3
    const int n  = n0 + nl;

    float a[4];
    #pragma unroll
    for (int q = 0; q < 4; q++) a[q] = sb[cg * 4 + q];

    #pragma unroll
    for (int k = 0; k < KW; k++) {
        #pragma unroll
        for (int ci = 0; ci < Cc; ci++) {
            float v = sr[ci][nl + k];
            float4 wv = *reinterpret_cast<const float4*>(&sws[(ci * KW + k) * Cc + cg * 4]);
            a[0] += v * wv.x; a[1] += v * wv.y; a[2] += v * wv.z; a[3] += v * wv.w;
        }
    }

    // stage into smem at fragment-relative offsets (scattered STS is cheap)
    const int slice_base = (n0 >> 6) * 1024 + ((n0 & 63) >> 3) * 128;
    #pragma unroll
    for (int q = 0; q < 4; q++) {
        int c = cg * 4 + q;
        cfrag[rt_off(n, c) - slice_base] = __uint_as_float(f2tf32(a[q]));
    }
    __syncthreads();

    // coalesced write-out: 128 threads x 1 float4 = the whole 512-float slice
    {
        const float4* cf4 = reinterpret_cast<const float4*>(cfrag);
        float4* dst4 = reinterpret_cast<float4*>(
            g_rt + (size_t)b * NIN * Cc + slice_base);
        dst4[t] = cf4[t];
    }

    // PDL: allow the dependent (gauss) grid to proceed past its wait
    asm volatile("griddepcontrol.launch_dependents;");
}

// ---------------------------------------------------------------------------
// Kernel 2: Gaussian transform as tf32 MMA, PDL-overlapped.
// Phase 1 (overlaps conv): ALL 64 A-fragment exps -> registers A[16][4].
// griddepcontrol.wait, THEN phase 2: Bf streamed from L2 (__ldcg, 4-deep
// rolling window) feeding the 32 MMAs. Epilogue unchanged (proven).
// grid (MT, B) = (16, 8) = 128 blocks, block 512 (16 warps).
// ---------------------------------------------------------------------------
__global__ void __launch_bounds__(GTHREADS, 1)
gauss_mma_kernel(const float* __restrict__ xc,
                 const float* __restrict__ xt,
                 const float* __restrict__ sigma,
                 const float* __restrict__ lw,
                 const float* __restrict__ lb,
                 float* __restrict__ out) {
    __shared__ __align__(16) float zred[KQ][MTILE][Cc];   // 16 KB partials
    __shared__ __align__(16) float shlwT[Cc * OUTC];      // 2 KB transposed [c][o]
    __shared__ float sh_nh[Cc];
    __shared__ int   sh_alleq;

    const int b  = blockIdx.y;
    const int mt = blockIdx.x;
    const int t  = threadIdx.x;
    const int l  = t & 31;
    const int w  = t >> 5;
    const int msub = w & 3;
    const int kq   = w >> 2;

    if (t < Cc) {
        float sg = sigma[t];
        sh_nh[t] = -0.5f * expf(-2.0f * sg) * LOG2E;
    }
    if (t == 0) {
        float s0 = sigma[0];
        int eq = 1;
        #pragma unroll
        for (int c = 1; c < Cc; c++) eq &= (sigma[c] == s0);
        sh_alleq = eq;
    }
    // transposed linear weights: shlwT[c*OUTC + o] = lw[o*Cc + c]
    if (t < Cc * OUTC) {
        int c = t >> 5, o = t & 31;
        shlwT[t] = lw[o * Cc + c];
    }
    __syncthreads();

    if (sh_alleq) {
        // ---- Phase 1 (conv-independent): compute all A-fragment exps ----
        const float nh = sh_nh[0];
        const int mrow = mt * MTILE + msub * 16 + (l >> 2);
        const float xm0 = __ldg(xt + (size_t)b * NOUT + mrow);
        const float xm1 = __ldg(xt + (size_t)b * NOUT + mrow + 8);

        const float* xcb = xc + (size_t)b * NIN + kq * 128;
        float xr0 = __ldg(xcb + l);
        float xr1 = __ldg(xcb + 32 + l);
        float xr2 = __ldg(xcb + 64 + l);
        float xr3 = __ldg(xcb + 96 + l);

        unsigned A[KSTEPS][4];
        #pragma unroll
        for (int ks = 0; ks < KSTEPS; ks++) {
            const float xsrc = (ks < 8) ? ((ks < 4) ? xr0 : xr1)
                                        : ((ks < 12) ? xr2 : xr3);
            const int srca = (ks & 3) * 8 + (l & 3);
            float xna = __shfl_sync(0xffffffffu, xsrc, srca);
            float xnb = __shfl_sync(0xffffffffu, xsrc, srca + 4);
            float d;
            // ex2 bits used directly as tf32 (HW truncates) — no CVT in chain
            d = xm0 - xna; A[ks][0] = __float_as_uint(ex2a(d * d * nh));
            d = xm1 - xna; A[ks][1] = __float_as_uint(ex2a(d * d * nh));
            d = xm0 - xnb; A[ks][2] = __float_as_uint(ex2a(d * d * nh));
            d = xm1 - xnb; A[ks][3] = __float_as_uint(ex2a(d * d * nh));
        }

        // ---- wait for conv ONLY now (exps already done, overlapped) ----
        asm volatile("griddepcontrol.wait;" ::: "memory");

        // ---- Phase 2: stream Bf from L2 through a rolling window + MMA ----
        const float4* Bg = reinterpret_cast<const float4*>(
            g_rt + (size_t)b * NIN * Cc + kq * 2048);
        float4 Bw[BWIN];
        #pragma unroll
        for (int j = 0; j < BWIN; j++)
            Bw[j] = __ldcg(&Bg[(j >> 3) * 256 + (j & 7) * 32 + l]);

        float D0[4] = {0.f, 0.f, 0.f, 0.f};
        float D1[4] = {0.f, 0.f, 0.f, 0.f};

        #pragma unroll
        for (int ks = 0; ks < KSTEPS; ks++) {
            float4 bf = Bw[ks & (BWIN - 1)];
            if (ks + BWIN < KSTEPS) {
                int j = ks + BWIN;
                Bw[ks & (BWIN - 1)] = __ldcg(&Bg[(j >> 3) * 256 + (j & 7) * 32 + l]);
            }
            mma_tf32(D0, A[ks], __float_as_uint(bf.x), __float_as_uint(bf.y));
            mma_tf32(D1, A[ks], __float_as_uint(bf.z), __float_as_uint(bf.w));
        }

        const int ml = msub * 16 + (l >> 2);
        const int c0 = (l & 3) * 2;
        *reinterpret_cast<float2*>(&zred[kq][ml][c0])         = make_float2(D0[0], D0[1]);
        *reinterpret_cast<float2*>(&zred[kq][ml + 8][c0])     = make_float2(D0[2], D0[3]);
        *reinterpret_cast<float2*>(&zred[kq][ml][c0 + 8])     = make_float2(D1[0], D1[1]);
        *reinterpret_cast<float2*>(&zred[kq][ml + 8][c0 + 8]) = make_float2(D1[2], D1[3]);
    } else {
        // ---- generic per-channel sigma fallback (correct, not fast) ----
        asm volatile("griddepcontrol.wait;" ::: "memory");
        float nhc[8];
        const int chalf = l & 1;
        #pragma unroll
        for (int j = 0; j < 8; j++) nhc[j] = sh_nh[chalf * 8 + j];
        const int mloc = msub * 16 + (l >> 1);
        const float xm = __ldg(xt + (size_t)b * NOUT + mt * MTILE + mloc);
        const float* rtb = g_rt + (size_t)b * NIN * Cc;
        float acc[8];
        #pragma unroll
        for (int j = 0; j < 8; j++) acc[j] = 0.0f;
        for (int i = 0; i < NIN / KQ; i++) {
            const int n = kq * (NIN / KQ) + i;
            float dx = xm - __ldg(xc + (size_t)b * NIN + n);
            float d  = dx * dx;
            #pragma unroll
            for (int j = 0; j < 8; j++) {
                int c = chalf * 8 + j;
                acc[j] += ex2a(d * nhc[j]) * __ldcg(rtb + rt_off(n, c));
            }
        }
        float* zp = &zred[kq][mloc][chalf * 8];
        *reinterpret_cast<float4*>(zp)     = make_float4(acc[0], acc[1], acc[2], acc[3]);
        *reinterpret_cast<float4*>(zp + 4) = make_float4(acc[4], acc[5], acc[6], acc[7]);
    }
    __syncthreads();

    // Stage A: fold 4 partial sets into set 0 (256 threads, 1 float4 each)
    {
        float4* rv = reinterpret_cast<float4*>(zred);
        const int NV = MTILE * Cc / 4;   // 256 slots per set
        if (t < NV) {
            float4 s = rv[t];
            #pragma unroll
            for (int q = 1; q < KQ; q++) {
                float4 p = rv[q * NV + t];
                s.x += p.x; s.y += p.y; s.z += p.z; s.w += p.w;
            }
            rv[t] = s;
        }
    }
    __syncthreads();

    // linear C -> OUT_C + bias: thread t -> (ml = t>>3, 4 outputs at og=(t&7)*4)
    {
        const int ml = t >> 3;            // 0..63
        const int og = (t & 7) * 4;       // 0..28
        float z[Cc];
        #pragma unroll
        for (int c = 0; c < Cc; c += 4) {
            float4 zv = *reinterpret_cast<const float4*>(&zred[0][ml][c]);
            z[c] = zv.x; z[c + 1] = zv.y; z[c + 2] = zv.z; z[c + 3] = zv.w;
        }
        float4 o4;
        o4.x = __ldg(lb + og + 0); o4.y = __ldg(lb + og + 1);
        o4.z = __ldg(lb + og + 2); o4.w = __ldg(lb + og + 3);
        #pragma unroll
        for (int c = 0; c < Cc; c++) {
            float zc = z[c];
            float4 wv = *reinterpret_cast<const float4*>(&shlwT[c * OUTC + og]);
            o4.x += zc * wv.x; o4.y += zc * wv.y;
            o4.z += zc * wv.z; o4.w += zc * wv.w;
        }
        *reinterpret_cast<float4*>(
            out + (((size_t)b * NOUT) + mt * MTILE + ml) * OUTC + og) = o4;
    }
}

// ---------------------------------------------------------------------------
// Launch. Inputs (metadata order):
// 0 r (8,16,512) | 1 x_context (8,512,1) | 2 y_context (unused) |
// 3 x_target (8,1024,1) | 4 conv_w (16,16,5) | 5 conv_b (16) |
// 6 sigma (16) | 7 lin_w (32,16) | 8 lin_b (32)  -> out (8,1024,32) f32
// Gauss launched with Programmatic Dependent Launch; its exp phase
// overlaps conv, griddepcontrol.wait guards only the g_rt reads.
// ---------------------------------------------------------------------------
extern "C" void kernel_launch(void* const* d_in, const int* in_sizes, int n_in,
                              void* d_out, int out_size) {
    const float* r      = (const float*)d_in[0];
    const float* xc     = (const float*)d_in[1];
    const float* xt     = (const float*)d_in[3];
    const float* conv_w = (const float*)d_in[4];
    const float* conv_b = (const float*)d_in[5];
    const float* sigma  = (const float*)d_in[6];
    const float* lin_w  = (const float*)d_in[7];
    const float* lin_b  = (const float*)d_in[8];
    float* out = (float*)d_out;

    conv_kernel<<<dim3(NIN / CNTILE, Bq), CTHREADS>>>(r, conv_w, conv_b);

    cudaLaunchConfig_t cfg = {};
    cfg.gridDim  = dim3(MT, Bq);
    cfg.blockDim = dim3(GTHREADS);
    cfg.dynamicSmemBytes = 0;
    cfg.stream = 0;
    cudaLaunchAttribute attrs[1];
    attrs[0].id = cudaLaunchAttributeProgrammaticStreamSerialization;
    attrs[0].val.programmaticStreamSerializationAllowed = 1;
    cfg.attrs = attrs;
    cfg.numAttrs = 1;
    cudaLaunchKernelEx(&cfg, gauss_mma_kernel, xc, xt, sigma, lin_w, lin_b, out);
}